// round 3
// baseline (speedup 1.0000x reference)
#include <cuda_runtime.h>
#include <math.h>

#define BSZ    2
#define LSEQ   2048
#define DMODEL 1024
#define DINNER 4096
#define DSTATE 16
#define DTRANK 64
#define NTOK   (BSZ*LSEQ)   // 4096
#define LN_EPS 1e-5f

// ---------------- scratch (static device arrays: the sanctioned path) -----------------
// g_h1 is dead after GEMM #3; dt (step 8) aliases it to save 64 MB.
__device__ float g_xn  [NTOK*DMODEL];     // 16 MB   layernorm output (reused)
__device__ float g_h1  [NTOK*DINNER];     // 64 MB   silu(w1 @ xn)  -> later: softplus dt
__device__ float g_x2  [NTOK*DMODEL];     // 16 MB   x after MLP residual
__device__ float g_xz  [NTOK*2*DINNER];   // 128 MB  in_proj output (u_pre | z)
__device__ float g_u   [NTOK*DINNER];     // 64 MB   silu(conv)
__device__ float g_xdbl[NTOK*96];         // 1.5 MB  x_proj output (dt_in | B | C)
__device__ float g_y   [NTOK*DINNER];     // 64 MB   gated scan output

// ---------------- layernorm: one block per token, 256 threads x float4 ----------------
__global__ void ln_kernel(const float* __restrict__ x, const float* __restrict__ g,
                          const float* __restrict__ b, float* __restrict__ o)
{
    __shared__ float red[8];
    __shared__ float s_mu, s_w;
    int t = blockIdx.x;
    int tid = threadIdx.x;
    const float4* xr = (const float4*)(x + (size_t)t * DMODEL);
    float4 v = xr[tid];

    float s = v.x + v.y + v.z + v.w;
    #pragma unroll
    for (int o_ = 16; o_; o_ >>= 1) s += __shfl_xor_sync(0xffffffffu, s, o_);
    if ((tid & 31) == 0) red[tid >> 5] = s;
    __syncthreads();
    if (tid < 32) {
        float q = (tid < 8) ? red[tid] : 0.f;
        #pragma unroll
        for (int o_ = 4; o_; o_ >>= 1) q += __shfl_xor_sync(0xffffffffu, q, o_);
        if (tid == 0) s_mu = q * (1.f / DMODEL);
    }
    __syncthreads();
    float mu = s_mu;
    float dx = v.x - mu, dy = v.y - mu, dz = v.z - mu, dw = v.w - mu;
    float sq = dx*dx + dy*dy + dz*dz + dw*dw;
    #pragma unroll
    for (int o_ = 16; o_; o_ >>= 1) sq += __shfl_xor_sync(0xffffffffu, sq, o_);
    if ((tid & 31) == 0) red[tid >> 5] = sq;
    __syncthreads();
    if (tid < 32) {
        float q = (tid < 8) ? red[tid] : 0.f;
        #pragma unroll
        for (int o_ = 4; o_; o_ >>= 1) q += __shfl_xor_sync(0xffffffffu, q, o_);
        if (tid == 0) s_w = rsqrtf(q * (1.f / DMODEL) + LN_EPS);
    }
    __syncthreads();
    float w = s_w;
    float4 gg = ((const float4*)g)[tid];
    float4 bb = ((const float4*)b)[tid];
    float4 out;
    out.x = dx * w * gg.x + bb.x;
    out.y = dy * w * gg.y + bb.y;
    out.z = dz * w * gg.z + bb.z;
    out.w = dw * w * gg.w + bb.w;
    ((float4*)(o + (size_t)t * DMODEL))[tid] = out;
}

// ---------------- generic SGEMM: C[M,N] = A[M,K(lda)] * W[N,K]^T, fused epilogues -----
// EPI: 0 none | 1 silu(c+bias) | 2 c+bias+res | 3 softplus(c+bias) | 4 c+res
#define TBM 128
#define TBN 128
#define TBK 16
#define SPAD 132

template<int EPI, bool SPLITK>
__global__ __launch_bounds__(256)
void sgemm_kernel(const float* __restrict__ A, int lda,
                  const float* __restrict__ W,
                  const float* __restrict__ bias,
                  const float* __restrict__ res,
                  float* __restrict__ C,
                  int M, int N, int K, int kChunk)
{
    __shared__ float As[TBK * SPAD];
    __shared__ float Ws[TBK * SPAD];

    int m0 = blockIdx.y * TBM;
    int n0 = blockIdx.x * TBN;
    int k0 = 0, k1 = K;
    if (SPLITK) { k0 = blockIdx.z * kChunk; k1 = min(K, k0 + kChunk); }

    int tid = threadIdx.x;
    int tx = tid & 15;        // 0..15 -> N direction (8 cols each)
    int ty = tid >> 4;        // 0..15 -> M direction (8 rows each)
    int lr = tid >> 2;        // loader row 0..63
    int lc = (tid & 3) * 4;   // loader col 0,4,8,12

    float acc[8][8];
    #pragma unroll
    for (int i = 0; i < 8; i++)
        #pragma unroll
        for (int j = 0; j < 8; j++) acc[i][j] = 0.f;

    for (int kt = k0; kt < k1; kt += TBK) {
        float4 a0 = *(const float4*)&A[(size_t)(m0 + lr)      * lda + kt + lc];
        float4 a1 = *(const float4*)&A[(size_t)(m0 + lr + 64) * lda + kt + lc];
        int na = n0 + lr, nb = n0 + lr + 64;
        float4 w0 = (na < N) ? *(const float4*)&W[(size_t)na * K + kt + lc]
                             : make_float4(0.f, 0.f, 0.f, 0.f);
        float4 w1 = (nb < N) ? *(const float4*)&W[(size_t)nb * K + kt + lc]
                             : make_float4(0.f, 0.f, 0.f, 0.f);
        __syncthreads();
        As[(lc+0)*SPAD + lr]      = a0.x; As[(lc+1)*SPAD + lr]      = a0.y;
        As[(lc+2)*SPAD + lr]      = a0.z; As[(lc+3)*SPAD + lr]      = a0.w;
        As[(lc+0)*SPAD + lr + 64] = a1.x; As[(lc+1)*SPAD + lr + 64] = a1.y;
        As[(lc+2)*SPAD + lr + 64] = a1.z; As[(lc+3)*SPAD + lr + 64] = a1.w;
        Ws[(lc+0)*SPAD + lr]      = w0.x; Ws[(lc+1)*SPAD + lr]      = w0.y;
        Ws[(lc+2)*SPAD + lr]      = w0.z; Ws[(lc+3)*SPAD + lr]      = w0.w;
        Ws[(lc+0)*SPAD + lr + 64] = w1.x; Ws[(lc+1)*SPAD + lr + 64] = w1.y;
        Ws[(lc+2)*SPAD + lr + 64] = w1.z; Ws[(lc+3)*SPAD + lr + 64] = w1.w;
        __syncthreads();

        #pragma unroll
        for (int k = 0; k < TBK; k++) {
            float ar[8], br[8];
            *(float4*)&ar[0] = *(float4*)&As[k*SPAD + ty*8];
            *(float4*)&ar[4] = *(float4*)&As[k*SPAD + ty*8 + 4];
            *(float4*)&br[0] = *(float4*)&Ws[k*SPAD + tx*8];
            *(float4*)&br[4] = *(float4*)&Ws[k*SPAD + tx*8 + 4];
            #pragma unroll
            for (int i = 0; i < 8; i++)
                #pragma unroll
                for (int j = 0; j < 8; j++)
                    acc[i][j] += ar[i] * br[j];
        }
    }

    #pragma unroll
    for (int i = 0; i < 8; i++) {
        int m = m0 + ty*8 + i;
        #pragma unroll
        for (int j = 0; j < 8; j++) {
            int n = n0 + tx*8 + j;
            if (n >= N) continue;
            float v = acc[i][j];
            if (SPLITK) {
                atomicAdd(&C[(size_t)m * N + n], v);
            } else {
                if (EPI == 1) { v += bias[n]; v = v / (1.f + expf(-v)); }
                else if (EPI == 2) { v += bias[n] + res[(size_t)m * N + n]; }
                else if (EPI == 3) { v += bias[n]; v = (v > 20.f) ? v : log1pf(expf(v)); }
                else if (EPI == 4) { v += res[(size_t)m * N + n]; }
                C[(size_t)m * N + n] = v;
            }
        }
    }
}

// ---------------- causal depthwise conv (k=4) + silu ---------------------------------
__global__ void conv_silu_kernel(const float* __restrict__ xz,
                                 const float* __restrict__ cw,
                                 const float* __restrict__ cb,
                                 float* __restrict__ u)
{
    int idx = blockIdx.x * 256 + threadIdx.x;     // t*DINNER + d
    int d = idx & (DINNER - 1);
    int t = idx >> 12;
    int l = t & (LSEQ - 1);
    float acc = cb[d];
    #pragma unroll
    for (int k = 0; k < 4; k++) {
        int ll = l - 3 + k;
        if (ll >= 0) acc += xz[(size_t)(t - 3 + k) * (2*DINNER) + d] * cw[d * 4 + k];
    }
    u[idx] = acc / (1.f + expf(-acc));
}

__global__ void zero_kernel(float* __restrict__ p, int n)
{
    int i = blockIdx.x * 256 + threadIdx.x;
    if (i < n) p[i] = 0.f;
}

// ---------------- selective scan: thread per (b,d), 16 states in regs, prefetched -----
__global__ __launch_bounds__(128)
void scan_kernel(const float* __restrict__ dt, const float* __restrict__ u,
                 const float* __restrict__ xz, const float* __restrict__ xdbl,
                 const float* __restrict__ A_log, const float* __restrict__ Dp,
                 float* __restrict__ y)
{
    int d = blockIdx.x * 128 + threadIdx.x;
    int b = blockIdx.y;
    float A[16], h[16];
    #pragma unroll
    for (int s = 0; s < 16; s++) {
        A[s] = -expf(A_log[d * 16 + s]);
        h[s] = 0.f;
    }
    float Dc = Dp[d];

    // prefetch token 0
    int t0 = b * LSEQ;
    float dtv = dt[(size_t)t0 * DINNER + d];
    float uv  = u [(size_t)t0 * DINNER + d];
    float zv  = xz[(size_t)t0 * (2*DINNER) + DINNER + d];
    float4 Bv0 = ((const float4*)(xdbl + t0 * 96 + 64))[0];
    float4 Bv1 = ((const float4*)(xdbl + t0 * 96 + 64))[1];
    float4 Bv2 = ((const float4*)(xdbl + t0 * 96 + 64))[2];
    float4 Bv3 = ((const float4*)(xdbl + t0 * 96 + 64))[3];
    float4 Cv0 = ((const float4*)(xdbl + t0 * 96 + 80))[0];
    float4 Cv1 = ((const float4*)(xdbl + t0 * 96 + 80))[1];
    float4 Cv2 = ((const float4*)(xdbl + t0 * 96 + 80))[2];
    float4 Cv3 = ((const float4*)(xdbl + t0 * 96 + 80))[3];

    for (int l = 0; l < LSEQ; l++) {
        int t = b * LSEQ + l;
        // issue next-token loads before computing current (latency hiding)
        float n_dt = 0.f, n_u = 0.f, n_z = 0.f;
        float4 nB0, nB1, nB2, nB3, nC0, nC1, nC2, nC3;
        if (l + 1 < LSEQ) {
            int tn = t + 1;
            n_dt = dt[(size_t)tn * DINNER + d];
            n_u  = u [(size_t)tn * DINNER + d];
            n_z  = xz[(size_t)tn * (2*DINNER) + DINNER + d];
            const float4* bp = (const float4*)(xdbl + tn * 96 + 64);
            const float4* cp = (const float4*)(xdbl + tn * 96 + 80);
            nB0 = bp[0]; nB1 = bp[1]; nB2 = bp[2]; nB3 = bp[3];
            nC0 = cp[0]; nC1 = cp[1]; nC2 = cp[2]; nC3 = cp[3];
        } else {
            nB0 = nB1 = nB2 = nB3 = make_float4(0.f,0.f,0.f,0.f);
            nC0 = nC1 = nC2 = nC3 = make_float4(0.f,0.f,0.f,0.f);
        }

        float Bv[16], Cv[16];
        ((float4*)Bv)[0] = Bv0; ((float4*)Bv)[1] = Bv1;
        ((float4*)Bv)[2] = Bv2; ((float4*)Bv)[3] = Bv3;
        ((float4*)Cv)[0] = Cv0; ((float4*)Cv)[1] = Cv1;
        ((float4*)Cv)[2] = Cv2; ((float4*)Cv)[3] = Cv3;

        float du = dtv * uv;
        float ys = 0.f;
        #pragma unroll
        for (int s = 0; s < 16; s++) {
            float dA = __expf(dtv * A[s]);
            h[s] = dA * h[s] + du * Bv[s];
            ys += h[s] * Cv[s];
        }
        float yy = ys + uv * Dc;
        float sg = zv / (1.f + __expf(-zv));
        y[(size_t)t * DINNER + d] = yy * sg;

        dtv = n_dt; uv = n_u; zv = n_z;
        Bv0 = nB0; Bv1 = nB1; Bv2 = nB2; Bv3 = nB3;
        Cv0 = nC0; Cv1 = nC1; Cv2 = nC2; Cv3 = nC3;
    }
}

// ---------------- launch --------------------------------------------------------------
extern "C" void kernel_launch(void* const* d_in, const int* in_sizes, int n_in,
                              void* d_out, int out_size)
{
    const float* x         = (const float*)d_in[0];
    const float* g1        = (const float*)d_in[1];
    const float* b1        = (const float*)d_in[2];
    const float* g2        = (const float*)d_in[3];
    const float* b2        = (const float*)d_in[4];
    const float* w1        = (const float*)d_in[5];
    const float* bias1     = (const float*)d_in[6];
    const float* w2        = (const float*)d_in[7];
    const float* bias2     = (const float*)d_in[8];
    const float* in_proj_w = (const float*)d_in[9];
    const float* conv_w    = (const float*)d_in[10];
    const float* conv_b    = (const float*)d_in[11];
    const float* x_proj_w  = (const float*)d_in[12];
    const float* dt_proj_w = (const float*)d_in[13];
    const float* dt_proj_b = (const float*)d_in[14];
    const float* A_log     = (const float*)d_in[15];
    const float* Dp        = (const float*)d_in[16];
    const float* out_proj_w= (const float*)d_in[17];
    float* out = (float*)d_out;

    float *xn, *h1, *x2, *xz, *u, *xdbl, *y;
    cudaGetSymbolAddress((void**)&xn,   g_xn);
    cudaGetSymbolAddress((void**)&h1,   g_h1);
    cudaGetSymbolAddress((void**)&x2,   g_x2);
    cudaGetSymbolAddress((void**)&xz,   g_xz);
    cudaGetSymbolAddress((void**)&u,    g_u);
    cudaGetSymbolAddress((void**)&xdbl, g_xdbl);
    cudaGetSymbolAddress((void**)&y,    g_y);
    float* dtbuf = h1;   // h1 is dead after GEMM #3; reuse as dt

    // 1. LN1
    ln_kernel<<<NTOK, 256>>>(x, g1, b1, xn);
    // 2. h1 = silu(xn @ w1^T + bias1)   [4096,4096] K=1024
    sgemm_kernel<1,false><<<dim3(DINNER/TBN, NTOK/TBM), 256>>>(
        xn, DMODEL, w1, bias1, nullptr, h1, NTOK, DINNER, DMODEL, 0);
    // 3. x2 = x + h1 @ w2^T + bias2     [4096,1024] K=4096
    sgemm_kernel<2,false><<<dim3(DMODEL/TBN, NTOK/TBM), 256>>>(
        h1, DINNER, w2, bias2, x, x2, NTOK, DMODEL, DINNER, 0);
    // 4. LN2
    ln_kernel<<<NTOK, 256>>>(x2, g2, b2, xn);
    // 5. xz = xn @ in_proj_w^T          [4096,8192] K=1024
    sgemm_kernel<0,false><<<dim3(2*DINNER/TBN, NTOK/TBM), 256>>>(
        xn, DMODEL, in_proj_w, nullptr, nullptr, xz, NTOK, 2*DINNER, DMODEL, 0);
    // 6. u = silu(causal depthwise conv of xz[:, :4096])
    conv_silu_kernel<<<(NTOK*DINNER)/256, 256>>>(xz, conv_w, conv_b, u);
    // 7. x_dbl = u @ x_proj_w^T         [4096,96] K=4096, split-K=8 atomic
    zero_kernel<<<(NTOK*96 + 255)/256, 256>>>(xdbl, NTOK*96);
    sgemm_kernel<0,true><<<dim3(1, NTOK/TBM, 8), 256>>>(
        u, DINNER, x_proj_w, nullptr, nullptr, xdbl, NTOK, 96, DINNER, DINNER/8);
    // 8. dt = softplus(x_dbl[:, :64] @ dt_proj_w^T + dt_proj_b)  [4096,4096] K=64, lda=96
    sgemm_kernel<3,false><<<dim3(DINNER/TBN, NTOK/TBM), 256>>>(
        xdbl, 96, dt_proj_w, dt_proj_b, nullptr, dtbuf, NTOK, DINNER, DTRANK, 0);
    // 9. scan + gate
    scan_kernel<<<dim3(DINNER/128, BSZ), 128>>>(dtbuf, u, xz, xdbl, A_log, Dp, y);
    // 10. out = x2 + y @ out_proj_w^T   [4096,1024] K=4096
    sgemm_kernel<4,false><<<dim3(DMODEL/TBN, NTOK/TBM), 256>>>(
        y, DINNER, out_proj_w, nullptr, x2, out, NTOK, DMODEL, DINNER, 0);
}

// round 4
// speedup vs baseline: 1.6551x; 1.6551x over previous
#include <cuda_runtime.h>
#include <cuda_bf16.h>
#include <math.h>
#include <stdint.h>

#define BSZ    2
#define LSEQ   2048
#define DMODEL 1024
#define DINNER 4096
#define DSTATE 16
#define DTRANK 64
#define NTOK   (BSZ*LSEQ)   // 4096
#define LN_EPS 1e-5f

// ---------------- scratch ------------------------------------------------------------
__device__ float g_xn  [NTOK*DMODEL];     // layernorm output (reused)
__device__ float g_h1  [NTOK*DINNER];     // silu(w1 @ xn) -> later softplus dt
__device__ float g_x2  [NTOK*DMODEL];     // x after MLP residual
__device__ float g_xz  [NTOK*2*DINNER];   // in_proj output (u_pre | z)
__device__ float g_u   [NTOK*DINNER];     // silu(conv)
__device__ float g_xdbl[NTOK*96];         // x_proj output (dt_in | B | C)
__device__ float g_y   [NTOK*DINNER];     // gated scan output

// ---------------- helpers ------------------------------------------------------------
__device__ __forceinline__ uint32_t smaddr(const void* p){
    uint32_t a;
    asm("{ .reg .u64 t; cvta.to.shared.u64 t, %1; cvt.u32.u64 %0, t; }" : "=r"(a) : "l"(p));
    return a;
}
__device__ __forceinline__ uint32_t bf2pack(float a, float b){
    __nv_bfloat162 t = __floats2bfloat162_rn(a, b);
    return *reinterpret_cast<uint32_t*>(&t);
}
__device__ __forceinline__ void ldsm4(uint32_t& r0,uint32_t& r1,uint32_t& r2,uint32_t& r3, uint32_t addr){
    asm volatile("ldmatrix.sync.aligned.m8n8.x4.shared.b16 {%0,%1,%2,%3},[%4];"
                 : "=r"(r0),"=r"(r1),"=r"(r2),"=r"(r3) : "r"(addr) : "memory");
}
__device__ __forceinline__ void ldsm2(uint32_t& r0,uint32_t& r1, uint32_t addr){
    asm volatile("ldmatrix.sync.aligned.m8n8.x2.shared.b16 {%0,%1},[%2];"
                 : "=r"(r0),"=r"(r1) : "r"(addr) : "memory");
}
__device__ __forceinline__ void mma_bf16(float* d, uint32_t a0,uint32_t a1,uint32_t a2,uint32_t a3,
                                         uint32_t b0,uint32_t b1){
    asm volatile("mma.sync.aligned.m16n8k16.row.col.f32.bf16.bf16.f32 "
                 "{%0,%1,%2,%3}, {%4,%5,%6,%7}, {%8,%9}, {%0,%1,%2,%3};"
                 : "+f"(d[0]),"+f"(d[1]),"+f"(d[2]),"+f"(d[3])
                 : "r"(a0),"r"(a1),"r"(a2),"r"(a3),"r"(b0),"r"(b1));
}

// store one row of 16 fp32 as bf16 hi/lo chunks with XOR swizzle.
// row layout: 8 chunks of 8 bf16 (16B). logical chunk = k/8 for hi, 4+k/8 for lo.
// physical chunk = logical ^ (row & 7).
__device__ __forceinline__ void store16(__nv_bfloat16* srow, int c0, int sw, const float (&f)[16]){
    uint4 v;
    v.x=bf2pack(f[0],f[1]);  v.y=bf2pack(f[2],f[3]);  v.z=bf2pack(f[4],f[5]);  v.w=bf2pack(f[6],f[7]);
    *(uint4*)&srow[(size_t)(((c0+0)^sw))*8] = v;
    v.x=bf2pack(f[8],f[9]);  v.y=bf2pack(f[10],f[11]); v.z=bf2pack(f[12],f[13]); v.w=bf2pack(f[14],f[15]);
    *(uint4*)&srow[(size_t)(((c0+1)^sw))*8] = v;
    float l[16];
    #pragma unroll
    for (int i=0;i<16;i++) l[i] = f[i] - __bfloat162float(__float2bfloat16(f[i]));
    v.x=bf2pack(l[0],l[1]);  v.y=bf2pack(l[2],l[3]);  v.z=bf2pack(l[4],l[5]);  v.w=bf2pack(l[6],l[7]);
    *(uint4*)&srow[(size_t)(((c0+4)^sw))*8] = v;
    v.x=bf2pack(l[8],l[9]);  v.y=bf2pack(l[10],l[11]); v.z=bf2pack(l[12],l[13]); v.w=bf2pack(l[14],l[15]);
    *(uint4*)&srow[(size_t)(((c0+5)^sw))*8] = v;
}

// ---------------- tensor-core GEMM: C[M,N] = A[M,K] @ W[N,K]^T (split-bf16 x3) --------
// CTA 128x128x32, 256 threads = 8 warps (2m x 4n), warp tile 64x32.
// EPI: 0 none | 1 silu(c+bias) | 2 c+bias+res | 4 c+res
template<int EPI>
__global__ __launch_bounds__(256, 1)
void tc_gemm(const float* __restrict__ A, const float* __restrict__ W,
             const float* __restrict__ bias, const float* __restrict__ res,
             float* __restrict__ C, int N, int K)
{
    __shared__ __align__(16) __nv_bfloat16 sA[128*64];
    __shared__ __align__(16) __nv_bfloat16 sW[128*64];

    const int tid  = threadIdx.x;
    const int lane = tid & 31;
    const int w    = tid >> 5;
    const int wm   = (w >> 2) * 64;
    const int wn   = (w & 3) * 32;
    const int bm   = blockIdx.y * 128;
    const int bn   = blockIdx.x * 128;

    const int lm  = tid >> 1;          // loader row 0..127
    const int lk  = (tid & 1) * 16;    // loader k offset 0/16
    const int c0  = lk >> 3;           // chunk base 0/2
    const int lsw = lm & 7;

    const float* Ag = A + (size_t)(bm + lm) * K + lk;
    const float* Wg = W + (size_t)(bn + lm) * K + lk;

    float acc[4][4][4];
    #pragma unroll
    for (int i=0;i<4;i++)
        #pragma unroll
        for (int j=0;j<4;j++)
            #pragma unroll
            for (int q=0;q<4;q++) acc[i][j][q]=0.f;

    const uint32_t sAa = smaddr(sA);
    const uint32_t sWa = smaddr(sW);
    const int nIter = K >> 5;

    float fa[16], fw[16];
    #pragma unroll
    for (int q=0;q<4;q++){
        *(float4*)&fa[q*4] = *(const float4*)(Ag + q*4);
        *(float4*)&fw[q*4] = *(const float4*)(Wg + q*4);
    }
    store16(&sA[lm*64], c0, lsw, fa);
    store16(&sW[lm*64], c0, lsw, fw);
    __syncthreads();

    for (int it = 0; it < nIter; ++it) {
        if (it + 1 < nIter) {
            Ag += 32; Wg += 32;
            #pragma unroll
            for (int q=0;q<4;q++){
                *(float4*)&fa[q*4] = *(const float4*)(Ag + q*4);
                *(float4*)&fw[q*4] = *(const float4*)(Wg + q*4);
            }
        }

        #pragma unroll
        for (int k16 = 0; k16 < 2; k16++) {
            uint32_t ah[4][4], al[4][4];
            #pragma unroll
            for (int mt=0; mt<4; mt++){
                int row = wm + mt*16 + (lane & 7) + ((lane >> 3) & 1) * 8;
                int ch  = 2*k16 + (lane >> 4);
                ldsm4(ah[mt][0],ah[mt][1],ah[mt][2],ah[mt][3],
                      sAa + (uint32_t)(row*64 + ((ch     ^ (row&7))*8)) * 2);
                ldsm4(al[mt][0],al[mt][1],al[mt][2],al[mt][3],
                      sAa + (uint32_t)(row*64 + (((ch+4) ^ (row&7))*8)) * 2);
            }
            uint32_t bh[4][2], bl[4][2];
            #pragma unroll
            for (int nt=0; nt<4; nt++){
                int nr = wn + nt*8 + (lane & 7);
                int ch = 2*k16 + ((lane >> 3) & 1);
                ldsm2(bh[nt][0],bh[nt][1],
                      sWa + (uint32_t)(nr*64 + ((ch     ^ (nr&7))*8)) * 2);
                ldsm2(bl[nt][0],bl[nt][1],
                      sWa + (uint32_t)(nr*64 + (((ch+4) ^ (nr&7))*8)) * 2);
            }
            #pragma unroll
            for (int mt=0; mt<4; mt++)
                #pragma unroll
                for (int nt=0; nt<4; nt++){
                    mma_bf16(acc[mt][nt], ah[mt][0],ah[mt][1],ah[mt][2],ah[mt][3], bh[nt][0],bh[nt][1]);
                    mma_bf16(acc[mt][nt], ah[mt][0],ah[mt][1],ah[mt][2],ah[mt][3], bl[nt][0],bl[nt][1]);
                    mma_bf16(acc[mt][nt], al[mt][0],al[mt][1],al[mt][2],al[mt][3], bh[nt][0],bh[nt][1]);
                }
        }

        __syncthreads();
        if (it + 1 < nIter) {
            store16(&sA[lm*64], c0, lsw, fa);
            store16(&sW[lm*64], c0, lsw, fw);
            __syncthreads();
        }
    }

    // epilogue
    const int g  = lane >> 2;
    const int cc = (lane & 3) * 2;
    #pragma unroll
    for (int mt=0; mt<4; mt++){
        #pragma unroll
        for (int nt=0; nt<4; nt++){
            int m = bm + wm + mt*16 + g;
            int n = bn + wn + nt*8 + cc;
            #pragma unroll
            for (int half=0; half<2; half++){
                int mm = m + half*8;
                float v0 = acc[mt][nt][half*2+0];
                float v1 = acc[mt][nt][half*2+1];
                if (EPI == 1) {
                    v0 += bias[n];   v0 = v0 / (1.f + expf(-v0));
                    v1 += bias[n+1]; v1 = v1 / (1.f + expf(-v1));
                } else if (EPI == 2) {
                    v0 += bias[n]   + res[(size_t)mm * N + n];
                    v1 += bias[n+1] + res[(size_t)mm * N + n + 1];
                } else if (EPI == 4) {
                    v0 += res[(size_t)mm * N + n];
                    v1 += res[(size_t)mm * N + n + 1];
                }
                float2 p = make_float2(v0, v1);
                *(float2*)&C[(size_t)mm * N + n] = p;
            }
        }
    }
}

// ---------------- layernorm ----------------------------------------------------------
__global__ void ln_kernel(const float* __restrict__ x, const float* __restrict__ g,
                          const float* __restrict__ b, float* __restrict__ o)
{
    __shared__ float red[8];
    __shared__ float s_mu, s_w;
    int t = blockIdx.x;
    int tid = threadIdx.x;
    const float4* xr = (const float4*)(x + (size_t)t * DMODEL);
    float4 v = xr[tid];

    float s = v.x + v.y + v.z + v.w;
    #pragma unroll
    for (int o_ = 16; o_; o_ >>= 1) s += __shfl_xor_sync(0xffffffffu, s, o_);
    if ((tid & 31) == 0) red[tid >> 5] = s;
    __syncthreads();
    if (tid < 32) {
        float q = (tid < 8) ? red[tid] : 0.f;
        #pragma unroll
        for (int o_ = 4; o_; o_ >>= 1) q += __shfl_xor_sync(0xffffffffu, q, o_);
        if (tid == 0) s_mu = q * (1.f / DMODEL);
    }
    __syncthreads();
    float mu = s_mu;
    float dx = v.x - mu, dy = v.y - mu, dz = v.z - mu, dw = v.w - mu;
    float sq = dx*dx + dy*dy + dz*dz + dw*dw;
    #pragma unroll
    for (int o_ = 16; o_; o_ >>= 1) sq += __shfl_xor_sync(0xffffffffu, sq, o_);
    if ((tid & 31) == 0) red[tid >> 5] = sq;
    __syncthreads();
    if (tid < 32) {
        float q = (tid < 8) ? red[tid] : 0.f;
        #pragma unroll
        for (int o_ = 4; o_; o_ >>= 1) q += __shfl_xor_sync(0xffffffffu, q, o_);
        if (tid == 0) s_w = rsqrtf(q * (1.f / DMODEL) + LN_EPS);
    }
    __syncthreads();
    float w = s_w;
    float4 gg = ((const float4*)g)[tid];
    float4 bb = ((const float4*)b)[tid];
    float4 out;
    out.x = dx * w * gg.x + bb.x;
    out.y = dy * w * gg.y + bb.y;
    out.z = dz * w * gg.z + bb.z;
    out.w = dw * w * gg.w + bb.w;
    ((float4*)(o + (size_t)t * DMODEL))[tid] = out;
}

// ---------------- SIMT SGEMM (kept for x_proj split-K and dt) -------------------------
#define TBM 128
#define TBN 128
#define TBK 16
#define SPAD 132

template<int EPI, bool SPLITK>
__global__ __launch_bounds__(256)
void sgemm_kernel(const float* __restrict__ A, int lda,
                  const float* __restrict__ W,
                  const float* __restrict__ bias,
                  const float* __restrict__ res,
                  float* __restrict__ C,
                  int M, int N, int K, int kChunk)
{
    __shared__ float As[TBK * SPAD];
    __shared__ float Ws[TBK * SPAD];

    int m0 = blockIdx.y * TBM;
    int n0 = blockIdx.x * TBN;
    int k0 = 0, k1 = K;
    if (SPLITK) { k0 = blockIdx.z * kChunk; k1 = min(K, k0 + kChunk); }

    int tid = threadIdx.x;
    int tx = tid & 15;
    int ty = tid >> 4;
    int lr = tid >> 2;
    int lc = (tid & 3) * 4;

    float acc[8][8];
    #pragma unroll
    for (int i = 0; i < 8; i++)
        #pragma unroll
        for (int j = 0; j < 8; j++) acc[i][j] = 0.f;

    for (int kt = k0; kt < k1; kt += TBK) {
        float4 a0 = *(const float4*)&A[(size_t)(m0 + lr)      * lda + kt + lc];
        float4 a1 = *(const float4*)&A[(size_t)(m0 + lr + 64) * lda + kt + lc];
        int na = n0 + lr, nb = n0 + lr + 64;
        float4 w0 = (na < N) ? *(const float4*)&W[(size_t)na * K + kt + lc]
                             : make_float4(0.f, 0.f, 0.f, 0.f);
        float4 w1 = (nb < N) ? *(const float4*)&W[(size_t)nb * K + kt + lc]
                             : make_float4(0.f, 0.f, 0.f, 0.f);
        __syncthreads();
        As[(lc+0)*SPAD + lr]      = a0.x; As[(lc+1)*SPAD + lr]      = a0.y;
        As[(lc+2)*SPAD + lr]      = a0.z; As[(lc+3)*SPAD + lr]      = a0.w;
        As[(lc+0)*SPAD + lr + 64] = a1.x; As[(lc+1)*SPAD + lr + 64] = a1.y;
        As[(lc+2)*SPAD + lr + 64] = a1.z; As[(lc+3)*SPAD + lr + 64] = a1.w;
        Ws[(lc+0)*SPAD + lr]      = w0.x; Ws[(lc+1)*SPAD + lr]      = w0.y;
        Ws[(lc+2)*SPAD + lr]      = w0.z; Ws[(lc+3)*SPAD + lr]      = w0.w;
        Ws[(lc+0)*SPAD + lr + 64] = w1.x; Ws[(lc+1)*SPAD + lr + 64] = w1.y;
        Ws[(lc+2)*SPAD + lr + 64] = w1.z; Ws[(lc+3)*SPAD + lr + 64] = w1.w;
        __syncthreads();

        #pragma unroll
        for (int k = 0; k < TBK; k++) {
            float ar[8], br[8];
            *(float4*)&ar[0] = *(float4*)&As[k*SPAD + ty*8];
            *(float4*)&ar[4] = *(float4*)&As[k*SPAD + ty*8 + 4];
            *(float4*)&br[0] = *(float4*)&Ws[k*SPAD + tx*8];
            *(float4*)&br[4] = *(float4*)&Ws[k*SPAD + tx*8 + 4];
            #pragma unroll
            for (int i = 0; i < 8; i++)
                #pragma unroll
                for (int j = 0; j < 8; j++)
                    acc[i][j] += ar[i] * br[j];
        }
    }

    #pragma unroll
    for (int i = 0; i < 8; i++) {
        int m = m0 + ty*8 + i;
        #pragma unroll
        for (int j = 0; j < 8; j++) {
            int n = n0 + tx*8 + j;
            if (n >= N) continue;
            float v = acc[i][j];
            if (SPLITK) {
                atomicAdd(&C[(size_t)m * N + n], v);
            } else {
                if (EPI == 1) { v += bias[n]; v = v / (1.f + expf(-v)); }
                else if (EPI == 2) { v += bias[n] + res[(size_t)m * N + n]; }
                else if (EPI == 3) { v += bias[n]; v = (v > 20.f) ? v : log1pf(expf(v)); }
                else if (EPI == 4) { v += res[(size_t)m * N + n]; }
                C[(size_t)m * N + n] = v;
            }
        }
    }
}

// ---------------- causal depthwise conv (k=4) + silu ---------------------------------
__global__ void conv_silu_kernel(const float* __restrict__ xz,
                                 const float* __restrict__ cw,
                                 const float* __restrict__ cb,
                                 float* __restrict__ u)
{
    int idx = blockIdx.x * 256 + threadIdx.x;
    int d = idx & (DINNER - 1);
    int t = idx >> 12;
    int l = t & (LSEQ - 1);
    float acc = cb[d];
    #pragma unroll
    for (int k = 0; k < 4; k++) {
        int ll = l - 3 + k;
        if (ll >= 0) acc += xz[(size_t)(t - 3 + k) * (2*DINNER) + d] * cw[d * 4 + k];
    }
    u[idx] = acc / (1.f + expf(-acc));
}

__global__ void zero_kernel(float* __restrict__ p, int n)
{
    int i = blockIdx.x * 256 + threadIdx.x;
    if (i < n) p[i] = 0.f;
}

// ---------------- selective scan ------------------------------------------------------
__global__ __launch_bounds__(128)
void scan_kernel(const float* __restrict__ dt, const float* __restrict__ u,
                 const float* __restrict__ xz, const float* __restrict__ xdbl,
                 const float* __restrict__ A_log, const float* __restrict__ Dp,
                 float* __restrict__ y)
{
    int d = blockIdx.x * 128 + threadIdx.x;
    int b = blockIdx.y;
    float A[16], h[16];
    #pragma unroll
    for (int s = 0; s < 16; s++) {
        A[s] = -expf(A_log[d * 16 + s]);
        h[s] = 0.f;
    }
    float Dc = Dp[d];

    int t0 = b * LSEQ;
    float dtv = dt[(size_t)t0 * DINNER + d];
    float uv  = u [(size_t)t0 * DINNER + d];
    float zv  = xz[(size_t)t0 * (2*DINNER) + DINNER + d];
    float4 Bv0 = ((const float4*)(xdbl + t0 * 96 + 64))[0];
    float4 Bv1 = ((const float4*)(xdbl + t0 * 96 + 64))[1];
    float4 Bv2 = ((const float4*)(xdbl + t0 * 96 + 64))[2];
    float4 Bv3 = ((const float4*)(xdbl + t0 * 96 + 64))[3];
    float4 Cv0 = ((const float4*)(xdbl + t0 * 96 + 80))[0];
    float4 Cv1 = ((const float4*)(xdbl + t0 * 96 + 80))[1];
    float4 Cv2 = ((const float4*)(xdbl + t0 * 96 + 80))[2];
    float4 Cv3 = ((const float4*)(xdbl + t0 * 96 + 80))[3];

    for (int l = 0; l < LSEQ; l++) {
        int t = b * LSEQ + l;
        float n_dt = 0.f, n_u = 0.f, n_z = 0.f;
        float4 nB0, nB1, nB2, nB3, nC0, nC1, nC2, nC3;
        if (l + 1 < LSEQ) {
            int tn = t + 1;
            n_dt = dt[(size_t)tn * DINNER + d];
            n_u  = u [(size_t)tn * DINNER + d];
            n_z  = xz[(size_t)tn * (2*DINNER) + DINNER + d];
            const float4* bp = (const float4*)(xdbl + tn * 96 + 64);
            const float4* cp = (const float4*)(xdbl + tn * 96 + 80);
            nB0 = bp[0]; nB1 = bp[1]; nB2 = bp[2]; nB3 = bp[3];
            nC0 = cp[0]; nC1 = cp[1]; nC2 = cp[2]; nC3 = cp[3];
        } else {
            nB0 = nB1 = nB2 = nB3 = make_float4(0.f,0.f,0.f,0.f);
            nC0 = nC1 = nC2 = nC3 = make_float4(0.f,0.f,0.f,0.f);
        }

        float Bv[16], Cv[16];
        ((float4*)Bv)[0] = Bv0; ((float4*)Bv)[1] = Bv1;
        ((float4*)Bv)[2] = Bv2; ((float4*)Bv)[3] = Bv3;
        ((float4*)Cv)[0] = Cv0; ((float4*)Cv)[1] = Cv1;
        ((float4*)Cv)[2] = Cv2; ((float4*)Cv)[3] = Cv3;

        float du = dtv * uv;
        float ys = 0.f;
        #pragma unroll
        for (int s = 0; s < 16; s++) {
            float dA = __expf(dtv * A[s]);
            h[s] = dA * h[s] + du * Bv[s];
            ys += h[s] * Cv[s];
        }
        float yy = ys + uv * Dc;
        float sg = zv / (1.f + __expf(-zv));
        y[(size_t)t * DINNER + d] = yy * sg;

        dtv = n_dt; uv = n_u; zv = n_z;
        Bv0 = nB0; Bv1 = nB1; Bv2 = nB2; Bv3 = nB3;
        Cv0 = nC0; Cv1 = nC1; Cv2 = nC2; Cv3 = nC3;
    }
}

// ---------------- launch --------------------------------------------------------------
extern "C" void kernel_launch(void* const* d_in, const int* in_sizes, int n_in,
                              void* d_out, int out_size)
{
    const float* x         = (const float*)d_in[0];
    const float* g1        = (const float*)d_in[1];
    const float* b1        = (const float*)d_in[2];
    const float* g2        = (const float*)d_in[3];
    const float* b2        = (const float*)d_in[4];
    const float* w1        = (const float*)d_in[5];
    const float* bias1     = (const float*)d_in[6];
    const float* w2        = (const float*)d_in[7];
    const float* bias2     = (const float*)d_in[8];
    const float* in_proj_w = (const float*)d_in[9];
    const float* conv_w    = (const float*)d_in[10];
    const float* conv_b    = (const float*)d_in[11];
    const float* x_proj_w  = (const float*)d_in[12];
    const float* dt_proj_w = (const float*)d_in[13];
    const float* dt_proj_b = (const float*)d_in[14];
    const float* A_log     = (const float*)d_in[15];
    const float* Dp        = (const float*)d_in[16];
    const float* out_proj_w= (const float*)d_in[17];
    float* out = (float*)d_out;

    float *xn, *h1, *x2, *xz, *u, *xdbl, *y;
    cudaGetSymbolAddress((void**)&xn,   g_xn);
    cudaGetSymbolAddress((void**)&h1,   g_h1);
    cudaGetSymbolAddress((void**)&x2,   g_x2);
    cudaGetSymbolAddress((void**)&xz,   g_xz);
    cudaGetSymbolAddress((void**)&u,    g_u);
    cudaGetSymbolAddress((void**)&xdbl, g_xdbl);
    cudaGetSymbolAddress((void**)&y,    g_y);
    float* dtbuf = h1;   // h1 dead after GEMM #3

    // 1. LN1
    ln_kernel<<<NTOK, 256>>>(x, g1, b1, xn);
    // 2. h1 = silu(xn @ w1^T + bias1)   [4096,4096] K=1024   (TC)
    tc_gemm<1><<<dim3(DINNER/128, NTOK/128), 256>>>(xn, w1, bias1, nullptr, h1, DINNER, DMODEL);
    // 3. x2 = x + h1 @ w2^T + bias2     [4096,1024] K=4096   (TC)
    tc_gemm<2><<<dim3(DMODEL/128, NTOK/128), 256>>>(h1, w2, bias2, x, x2, DMODEL, DINNER);
    // 4. LN2
    ln_kernel<<<NTOK, 256>>>(x2, g2, b2, xn);
    // 5. xz = xn @ in_proj_w^T          [4096,8192] K=1024   (TC)
    tc_gemm<0><<<dim3(2*DINNER/128, NTOK/128), 256>>>(xn, in_proj_w, nullptr, nullptr, xz, 2*DINNER, DMODEL);
    // 6. u = silu(causal depthwise conv of xz[:, :4096])
    conv_silu_kernel<<<(NTOK*DINNER)/256, 256>>>(xz, conv_w, conv_b, u);
    // 7. x_dbl = u @ x_proj_w^T         [4096,96] K=4096, split-K=8 atomic (SIMT)
    zero_kernel<<<(NTOK*96 + 255)/256, 256>>>(xdbl, NTOK*96);
    sgemm_kernel<0,true><<<dim3(1, NTOK/TBM, 8), 256>>>(
        u, DINNER, x_proj_w, nullptr, nullptr, xdbl, NTOK, 96, DINNER, DINNER/8);
    // 8. dt = softplus(x_dbl[:, :64] @ dt_proj_w^T + dt_proj_b)  K=64, lda=96 (SIMT)
    sgemm_kernel<3,false><<<dim3(DINNER/TBN, NTOK/TBM), 256>>>(
        xdbl, 96, dt_proj_w, dt_proj_b, nullptr, dtbuf, NTOK, DINNER, DTRANK, 0);
    // 9. scan + gate
    scan_kernel<<<dim3(DINNER/128, BSZ), 128>>>(dtbuf, u, xz, xdbl, A_log, Dp, y);
    // 10. out = x2 + y @ out_proj_w^T   [4096,1024] K=4096   (TC)
    tc_gemm<4><<<dim3(DMODEL/128, NTOK/128), 256>>>(y, out_proj_w, nullptr, x2, out, DMODEL, DINNER);
}